// round 3
// baseline (speedup 1.0000x reference)
#include <cuda_runtime.h>
#include <cstdint>

// Problem constants (shapes fixed by the dataset)
#define NROWS   65536
#define DIM     256
#define NBOOK   16
#define DSUB    16
#define KWORDS  256
#define ZPAD    20          // smem row stride in floats (16 data + 4 pad, conflict-free STS)

typedef unsigned long long u64;

// ---- packed f32x2 helpers (ptxas never emits FFMA2 from C++; PTX only) ----
__device__ __forceinline__ u64 fma2(u64 a, u64 b, u64 c) {
    u64 d; asm("fma.rn.f32x2 %0, %1, %2, %3;" : "=l"(d) : "l"(a), "l"(b), "l"(c));
    return d;
}
__device__ __forceinline__ u64 add2(u64 a, u64 b) {
    u64 d; asm("add.rn.f32x2 %0, %1, %2;" : "=l"(d) : "l"(a), "l"(b));
    return d;
}
__device__ __forceinline__ u64 pack2(float lo, float hi) {
    u64 d; asm("mov.b64 %0, {%1, %2};" : "=l"(d) : "f"(lo), "f"(hi));
    return d;
}
__device__ __forceinline__ void unpack2(u64 v, float& lo, float& hi) {
    asm("mov.b64 {%0, %1}, %2;" : "=f"(lo), "=f"(hi) : "l"(v));
}
__device__ __forceinline__ float ex2f(float x) {
    float y; asm("ex2.approx.f32 %0, %1;" : "=f"(y) : "f"(x));
    return y;
}

union U16 {
    float4 v[4];
    u64    u[8];
    float  f[16];
};

// One block = (row tile of 256, one book). Each thread owns one row.
// Codebook sub-vectors for this book are L2-normalized into smem once,
// then broadcast-read (conflict-free) by all threads in the k-loop.
__global__ void __launch_bounds__(256, 3) softassign_kernel(
    const float* __restrict__ features,
    const float* __restrict__ Zw,
    const float* __restrict__ alphap,
    float* __restrict__ out)
{
    __shared__ float zsm[KWORDS * ZPAD];   // 20480 bytes

    const int b   = blockIdx.y;
    const int tid = threadIdx.x;

    // ---- prologue: intranorm this book's 256 codeword sub-vectors into smem ----
    {
        const float4* zr = (const float4*)(Zw + (size_t)tid * DIM + b * DSUB);
        U16 Z;
        Z.v[0] = zr[0]; Z.v[1] = zr[1]; Z.v[2] = zr[2]; Z.v[3] = zr[3];
        float n2 = 0.f;
        #pragma unroll
        for (int j = 0; j < 16; j++) n2 += Z.f[j] * Z.f[j];
        const float inv = 1.0f / fmaxf(sqrtf(n2), 1e-12f);
        #pragma unroll
        for (int j = 0; j < 16; j++) Z.f[j] *= inv;
        float4* dst = (float4*)(zsm + tid * ZPAD);   // stride 20 floats -> conflict-free STS.128
        dst[0] = Z.v[0]; dst[1] = Z.v[1]; dst[2] = Z.v[2]; dst[3] = Z.v[3];
    }
    __syncthreads();

    // ---- load this thread's sub-vector x_b (16 floats) ----
    const int n = blockIdx.x * 256 + tid;
    U16 X;
    {
        const float4* xr = (const float4*)(features + (size_t)n * DIM + b * DSUB);
        X.v[0] = xr[0]; X.v[1] = xr[1]; X.v[2] = xr[2]; X.v[3] = xr[3];
    }
    float xn2 = 0.f;
    #pragma unroll
    for (int j = 0; j < 16; j++) xn2 += X.f[j] * X.f[j];

    // softmax(alpha*dot): shift by alpha*||x_b|| (dot <= ||x_b|| since z_k unit)
    // -> single pass, no max tracking, no overflow. Shift cancels in softmax.
    const float alpha = __ldg(alphap);
    const float c1 = alpha * 1.4426950408889634f;         // alpha * log2(e)
    const float c0 = -sqrtf(xn2) * c1;

    u64 acc[8];
    #pragma unroll
    for (int j = 0; j < 8; j++) acc[j] = 0ull;            // (0.0f, 0.0f)
    float l = 0.f;

    #pragma unroll 4
    for (int k = 0; k < KWORDS; k++) {
        U16 Z;
        const float4* z4 = (const float4*)(zsm + k * ZPAD);   // broadcast LDS.128 x4
        Z.v[0] = z4[0]; Z.v[1] = z4[1]; Z.v[2] = z4[2]; Z.v[3] = z4[3];

        // dot(x, z_k): 8 packed FMAs on 4 independent chains
        u64 s0 = fma2(X.u[0], Z.u[0], 0ull);
        u64 s1 = fma2(X.u[1], Z.u[1], 0ull);
        u64 s2 = fma2(X.u[2], Z.u[2], 0ull);
        u64 s3 = fma2(X.u[3], Z.u[3], 0ull);
        s0 = fma2(X.u[4], Z.u[4], s0);
        s1 = fma2(X.u[5], Z.u[5], s1);
        s2 = fma2(X.u[6], Z.u[6], s2);
        s3 = fma2(X.u[7], Z.u[7], s3);
        s0 = add2(s0, s1);
        s2 = add2(s2, s3);
        s0 = add2(s0, s2);
        float lo, hi; unpack2(s0, lo, hi);
        const float s = lo + hi;

        const float e = ex2f(fmaf(s, c1, c0));   // exp(alpha*(s - ||x||)) in (0,1]
        l += e;
        const u64 ee = pack2(e, e);
        #pragma unroll
        for (int j = 0; j < 8; j++) acc[j] = fma2(Z.u[j], ee, acc[j]);
    }

    // desc = acc / l; out = desc / max(||desc||, 1e-12)  ==  acc / max(||acc||, 1e-12 * l)
    U16 A;
    #pragma unroll
    for (int j = 0; j < 8; j++) A.u[j] = acc[j];
    float n2 = 0.f;
    #pragma unroll
    for (int j = 0; j < 16; j++) n2 += A.f[j] * A.f[j];
    const float scale = 1.0f / fmaxf(sqrtf(n2), 1e-12f * l);
    #pragma unroll
    for (int j = 0; j < 16; j++) A.f[j] *= scale;

    float4* op = (float4*)(out + (size_t)n * DIM + b * DSUB);
    op[0] = A.v[0]; op[1] = A.v[1]; op[2] = A.v[2]; op[3] = A.v[3];
}

extern "C" void kernel_launch(void* const* d_in, const int* in_sizes, int n_in,
                              void* d_out, int out_size)
{
    const float* features = (const float*)d_in[0];   // [65536, 256] f32
    const float* Zw       = (const float*)d_in[1];   // [256, 256]  f32
    // d_in[2] = n_book (unused, compile-time 16)
    const float* alphap   = (const float*)d_in[3];   // scalar f32
    float* out = (float*)d_out;

    dim3 grid(NROWS / 256, NBOOK);
    softassign_kernel<<<grid, 256>>>(features, Zw, alphap, out);
}

// round 11
// speedup vs baseline: 2.3053x; 2.3053x over previous
#include <cuda_runtime.h>
#include <cuda_bf16.h>
#include <cstdint>

#define NROWS   65536
#define DIM     256
#define CTAROWS 1024
#define TM      128
#define TILES   8
#define THREADS 256

// smem byte offsets (48B / 528B padded rows -> conflict-free LDS.32 frags)
#define ZB1B 0        // Zb  [256 cw][16 dim] bf16, 48B rows
#define ZB1S 12288    // Zs
#define ZTB  24576    // Zb^T [16 dim][256 cw] bf16, 528B rows
#define ZTS  33024    // Zs^T
#define XB   41472    // Xb  [128 row][16 dim] bf16, 48B rows
#define XS   47616    // Xs
#define C0O  53760    // 128 f32: -C1*||x_row||
#define SMEM_TOTAL 54272

static __device__ __forceinline__ void mma16816(float* d, const uint32_t* a,
                                                uint32_t b0, uint32_t b1, const float* c) {
    asm volatile("mma.sync.aligned.m16n8k16.row.col.f32.bf16.bf16.f32 "
        "{%0,%1,%2,%3}, {%4,%5,%6,%7}, {%8,%9}, {%10,%11,%12,%13};"
        : "=f"(d[0]), "=f"(d[1]), "=f"(d[2]), "=f"(d[3])
        : "r"(a[0]), "r"(a[1]), "r"(a[2]), "r"(a[3]), "r"(b0), "r"(b1),
          "f"(c[0]), "f"(c[1]), "f"(c[2]), "f"(c[3]));
}
static __device__ __forceinline__ uint32_t cvt_bf2(float lo, float hi) {
    uint32_t r; asm("cvt.rn.bf16x2.f32 %0, %1, %2;" : "=r"(r) : "f"(hi), "f"(lo)); return r;
}
static __device__ __forceinline__ float ex2f(float x) {
    float y; asm("ex2.approx.f32 %0, %1;" : "=f"(y) : "f"(x)); return y;
}
// split pair (v0,v1) -> big bf16x2 + small (residual) bf16x2
static __device__ __forceinline__ void split2(float v0, float v1, uint32_t& big, uint32_t& small) {
    big = cvt_bf2(v0, v1);
    float r0 = v0 - __uint_as_float(big << 16);
    float r1 = v1 - __uint_as_float(big & 0xFFFF0000u);
    small = cvt_bf2(r0, r1);
}

__global__ void __launch_bounds__(THREADS, 2) softassign_mma(
    const float* __restrict__ feat, const float* __restrict__ Zw,
    const float* __restrict__ alphap, float* __restrict__ out)
{
    extern __shared__ char sm[];
    const int tid = threadIdx.x, wid = tid >> 5, lane = tid & 31;
    const int r4 = lane >> 2, q = lane & 3;
    const int b = blockIdx.y;
    const float C1 = __ldg(alphap) * 1.4426950408889634f;

    // ---- Z prep (once per CTA): thread = codeword ----
    {
        const int k = tid;
        const float4* zr = (const float4*)(Zw + (size_t)k * DIM + b * 16);
        float z[16]; float4 t0 = zr[0], t1 = zr[1], t2 = zr[2], t3 = zr[3];
        z[0]=t0.x;z[1]=t0.y;z[2]=t0.z;z[3]=t0.w; z[4]=t1.x;z[5]=t1.y;z[6]=t1.z;z[7]=t1.w;
        z[8]=t2.x;z[9]=t2.y;z[10]=t2.z;z[11]=t2.w; z[12]=t3.x;z[13]=t3.y;z[14]=t3.z;z[15]=t3.w;
        float n2 = 0.f;
        #pragma unroll
        for (int j = 0; j < 16; j++) n2 += z[j] * z[j];
        const float inv = 1.0f / fmaxf(sqrtf(n2), 1e-12f);
        #pragma unroll
        for (int p = 0; p < 8; p++) {
            uint32_t big, small;
            split2(z[2*p] * inv, z[2*p+1] * inv, big, small);
            *(uint32_t*)(sm + ZB1B + k * 48 + p * 4) = big;
            *(uint32_t*)(sm + ZB1S + k * 48 + p * 4) = small;
            *(uint16_t*)(sm + ZTB + (2*p)   * 528 + k * 2) = (uint16_t)big;
            *(uint16_t*)(sm + ZTB + (2*p+1) * 528 + k * 2) = (uint16_t)(big >> 16);
            *(uint16_t*)(sm + ZTS + (2*p)   * 528 + k * 2) = (uint16_t)small;
            *(uint16_t*)(sm + ZTS + (2*p+1) * 528 + k * 2) = (uint16_t)(small >> 16);
        }
    }
    __syncthreads();

    for (int tile = 0; tile < TILES; tile++) {
        const int rowbase = blockIdx.x * CTAROWS + tile * TM;

        // ---- X prep: threads 0..127, one row each ----
        if (tid < TM) {
            const float4* xr = (const float4*)(feat + (size_t)(rowbase + tid) * DIM + b * 16);
            float x[16]; float4 t0 = xr[0], t1 = xr[1], t2 = xr[2], t3 = xr[3];
            x[0]=t0.x;x[1]=t0.y;x[2]=t0.z;x[3]=t0.w; x[4]=t1.x;x[5]=t1.y;x[6]=t1.z;x[7]=t1.w;
            x[8]=t2.x;x[9]=t2.y;x[10]=t2.z;x[11]=t2.w; x[12]=t3.x;x[13]=t3.y;x[14]=t3.z;x[15]=t3.w;
            float n2 = 0.f;
            #pragma unroll
            for (int j = 0; j < 16; j++) n2 += x[j] * x[j];
            *(float*)(sm + C0O + tid * 4) = -C1 * sqrtf(n2);
            #pragma unroll
            for (int p = 0; p < 8; p++) {
                uint32_t big, small;
                split2(x[2*p], x[2*p+1], big, small);
                *(uint32_t*)(sm + XB + tid * 48 + p * 4) = big;
                *(uint32_t*)(sm + XS + tid * 48 + p * 4) = small;
            }
        }
        __syncthreads();

        // ---- per warp: 16 rows (wid*16..) x this book ----
        uint32_t Ab[4], As[4];
        {
            const char* xb = sm + XB + (wid * 16 + r4) * 48 + q * 4;
            const char* xs = sm + XS + (wid * 16 + r4) * 48 + q * 4;
            Ab[0] = *(const uint32_t*)(xb);            As[0] = *(const uint32_t*)(xs);
            Ab[1] = *(const uint32_t*)(xb + 8 * 48);   As[1] = *(const uint32_t*)(xs + 8 * 48);
            Ab[2] = *(const uint32_t*)(xb + 16);       As[2] = *(const uint32_t*)(xs + 16);
            Ab[3] = *(const uint32_t*)(xb + 8*48+16);  As[3] = *(const uint32_t*)(xs + 8*48+16);
        }
        const float c0a = *(const float*)(sm + C0O + (wid * 16 + r4) * 4);
        const float c0b = *(const float*)(sm + C0O + (wid * 16 + r4 + 8) * 4);

        float D0[4] = {0,0,0,0}, D1[4] = {0,0,0,0};
        float l0 = 0.f, l1 = 0.f;

        #pragma unroll 1
        for (int c = 0; c < 4; c++) {       // 64 codewords per chunk
            const int cwb = c * 64;
            float S[8][4];
            #pragma unroll
            for (int j = 0; j < 8; j++) { S[j][0]=0; S[j][1]=0; S[j][2]=0; S[j][3]=0; }

            // MMA1: S = Xb*Zb + Xb*Zs + Xs*Zb
            #pragma unroll
            for (int j = 0; j < 8; j++) {
                const int cw = cwb + 8 * j + r4;
                uint32_t bb0 = *(const uint32_t*)(sm + ZB1B + cw * 48 + q * 4);
                uint32_t bb1 = *(const uint32_t*)(sm + ZB1B + cw * 48 + q * 4 + 16);
                uint32_t bs0 = *(const uint32_t*)(sm + ZB1S + cw * 48 + q * 4);
                uint32_t bs1 = *(const uint32_t*)(sm + ZB1S + cw * 48 + q * 4 + 16);
                mma16816(S[j], Ab, bb0, bb1, S[j]);
                mma16816(S[j], Ab, bs0, bs1, S[j]);
                mma16816(S[j], As, bb0, bb1, S[j]);
            }

            // epilogue + MMA2 per k16 tile (C tiles 2t,2t+1 -> A frag)
            #pragma unroll
            for (int t = 0; t < 4; t++) {
                float e0 = ex2f(fmaf(S[2*t][0],   C1, c0a));
                float e1 = ex2f(fmaf(S[2*t][1],   C1, c0a));
                float e2 = ex2f(fmaf(S[2*t][2],   C1, c0b));
                float e3 = ex2f(fmaf(S[2*t][3],   C1, c0b));
                float e4 = ex2f(fmaf(S[2*t+1][0], C1, c0a));
                float e5 = ex2f(fmaf(S[2*t+1][1], C1, c0a));
                float e6 = ex2f(fmaf(S[2*t+1][2], C1, c0b));
                float e7 = ex2f(fmaf(S[2*t+1][3], C1, c0b));
                l0 += (e0 + e1) + (e4 + e5);
                l1 += (e2 + e3) + (e6 + e7);
                uint32_t sb[4], ss[4];
                split2(e0, e1, sb[0], ss[0]);
                split2(e2, e3, sb[1], ss[1]);
                split2(e4, e5, sb[2], ss[2]);
                split2(e6, e7, sb[3], ss[3]);

                const int kb = (cwb + 16 * t + 2 * q) * 2;   // byte offset of cw pair
                const char* ztb0 = sm + ZTB + r4 * 528 + kb;
                const char* zts0 = sm + ZTS + r4 * 528 + kb;
                uint32_t nb0 = *(const uint32_t*)(ztb0);
                uint32_t nb1 = *(const uint32_t*)(ztb0 + 16);
                uint32_t ns0 = *(const uint32_t*)(zts0);
                uint32_t ns1 = *(const uint32_t*)(zts0 + 16);
                uint32_t mb0 = *(const uint32_t*)(ztb0 + 8 * 528);
                uint32_t mb1 = *(const uint32_t*)(ztb0 + 8 * 528 + 16);
                uint32_t ms0 = *(const uint32_t*)(zts0 + 8 * 528);
                uint32_t ms1 = *(const uint32_t*)(zts0 + 8 * 528 + 16);

                mma16816(D0, sb, nb0, nb1, D0);
                mma16816(D0, sb, ns0, ns1, D0);
                mma16816(D0, ss, nb0, nb1, D0);
                mma16816(D1, sb, mb0, mb1, D1);
                mma16816(D1, sb, ms0, ms1, D1);
                mma16816(D1, ss, mb0, mb1, D1);
            }
        }

        // ---- reduce l over the 4-lane col groups ----
        l0 += __shfl_xor_sync(0xFFFFFFFFu, l0, 1); l0 += __shfl_xor_sync(0xFFFFFFFFu, l0, 2);
        l1 += __shfl_xor_sync(0xFFFFFFFFu, l1, 1); l1 += __shfl_xor_sync(0xFFFFFFFFu, l1, 2);

        // ---- normalize + store ----
        float na = D0[0]*D0[0] + D0[1]*D0[1] + D1[0]*D1[0] + D1[1]*D1[1];
        na += __shfl_xor_sync(0xFFFFFFFFu, na, 1); na += __shfl_xor_sync(0xFFFFFFFFu, na, 2);
        float nb = D0[2]*D0[2] + D0[3]*D0[3] + D1[2]*D1[2] + D1[3]*D1[3];
        nb += __shfl_xor_sync(0xFFFFFFFFu, nb, 1); nb += __shfl_xor_sync(0xFFFFFFFFu, nb, 2);
        const float sca = 1.0f / fmaxf(sqrtf(na), 1e-12f * l0);
        const float scb = 1.0f / fmaxf(sqrtf(nb), 1e-12f * l1);

        {
            const int rowA = rowbase + wid * 16 + r4;
            float2* oA = (float2*)(out + (size_t)rowA * DIM + b * 16 + 2 * q);
            oA[0] = make_float2(D0[0] * sca, D0[1] * sca);
            oA[4] = make_float2(D1[0] * sca, D1[1] * sca);     // +8 floats
            float2* oB = (float2*)(out + (size_t)(rowA + 8) * DIM + b * 16 + 2 * q);
            oB[0] = make_float2(D0[2] * scb, D0[3] * scb);
            oB[4] = make_float2(D1[2] * scb, D1[3] * scb);
        }
        __syncthreads();   // X smem reused next tile
    }
}

extern "C" void kernel_launch(void* const* d_in, const int* in_sizes, int n_in,
                              void* d_out, int out_size)
{
    const float* feat  = (const float*)d_in[0];
    const float* Zw    = (const float*)d_in[1];
    const float* alphp = (const float*)d_in[3];
    float* out = (float*)d_out;
    cudaFuncSetAttribute(softassign_mma, cudaFuncAttributeMaxDynamicSharedMemorySize, SMEM_TOTAL);
    dim3 grid(NROWS / CTAROWS, 16);
    softassign_mma<<<grid, THREADS, SMEM_TOTAL>>>(feat, Zw, alphp, out);
}